// round 16
// baseline (speedup 1.0000x reference)
#include <cuda_runtime.h>
#include <cuda_bf16.h>
#include <math.h>
#include <stdint.h>

#define NN   65536
#define KX   512
#define AA   64
#define DD   8
#define PP   96
#define NB2  (NN/128)
#define MOMW (AA + AA*AA)
#define WFW  10464

// ---------------- scratch ----------------
__device__ __align__(16) float g_t  [(size_t)NN*AA];
__device__ __align__(16) float g_rep[(size_t)NN*AA];
__device__ __align__(16) float g_part[(size_t)NB2*MOMW];
__device__ __align__(16) float g_p2[8*MOMW];
__device__ __align__(16) uint32_t g_Wf[DD*WFW];
__device__ __align__(16) uint32_t g_Bf[8*4096];         // packed shz frags per k-chunk
__device__ __align__(16) float g_Y[(size_t)DD*NN*PP];   // planar tower outputs

__device__ __forceinline__ float eluf(float v) { return v > 0.f ? v : expm1f(v); }

__device__ __forceinline__ uint32_t pack2(float f0, float f1, uint32_t* lo) {
    __nv_bfloat16 h0 = __float2bfloat16(f0);
    __nv_bfloat16 h1 = __float2bfloat16(f1);
    __nv_bfloat16 l0 = __float2bfloat16(f0 - __bfloat162float(h0));
    __nv_bfloat16 l1 = __float2bfloat16(f1 - __bfloat162float(h1));
    *lo = (uint32_t)__bfloat16_as_ushort(l0) | ((uint32_t)__bfloat16_as_ushort(l1) << 16);
    return (uint32_t)__bfloat16_as_ushort(h0) | ((uint32_t)__bfloat16_as_ushort(h1) << 16);
}
__device__ __forceinline__ void mma_bf16(float* c, const uint32_t* a, const uint32_t* b) {
    asm volatile("mma.sync.aligned.m16n8k16.row.col.f32.bf16.bf16.f32 "
                 "{%0,%1,%2,%3}, {%4,%5,%6,%7}, {%8,%9}, {%0,%1,%2,%3};"
                 : "+f"(c[0]), "+f"(c[1]), "+f"(c[2]), "+f"(c[3])
                 : "r"(a[0]), "r"(a[1]), "r"(a[2]), "r"(a[3]), "r"(b[0]), "r"(b[1]));
}
// A-frag word index for m16n8k16; (row, col2) col2 even.
__device__ __forceinline__ int afragw(int row, int col2) {
    int m32 = row >> 5, mt = (row >> 4) & 1, ks = col2 >> 4;
    int rI = row & 15, cI = col2 & 15;
    int ln = (rI & 7) * 4 + ((cI >> 1) & 3);
    int j  = ((cI >> 3) << 1) | (rI >> 3);
    return (((m32 * 4 + ks) * 32 + ln) * 2 + mt) * 4 + j;
}

// ================= Kprep_b: pack shz chunk kc into fragment hi/lo planes ===========
__global__ __launch_bounds__(256) void kprep_b(const float* __restrict__ Bz) {
    __shared__ float Braw[64 * 65];
    int kc = blockIdx.x, tid = threadIdx.x;
    for (int l = tid; l < 4096; l += 256) {
        int k = l >> 6, n = l & 63;
        Braw[k * 65 + n] = Bz[(size_t)(kc * 64 + k) * AA + n];
    }
    __syncthreads();
    uint32_t* dst = g_Bf + kc * 4096;
    for (int l = tid; l < 2048; l += 256) {
        int n = l >> 5, k2 = (l & 31) * 2;
        uint32_t lo, hi = pack2(Braw[k2 * 65 + n], Braw[(k2 + 1) * 65 + n], &lo);
        int wn_ = n >> 4, nt = (n >> 3) & 1, nn = n & 7;
        int ks = k2 >> 4, kI = k2 & 15;
        int ln = nn * 4 + ((kI >> 1) & 3), j = kI >> 3;
        int w = (((wn_ * 4 + ks) * 2 + nt) * 32 + ln) * 2 + j;
        dst[w] = hi; dst[2048 + w] = lo;
    }
}

// ================= K1m: t = normalize_rows(x @ shz), compensated bf16 MMA ==========
#define K1_SMEM (16576 * 4)
__global__ __launch_bounds__(512, 1) void k1m(const float* __restrict__ x) {
    extern __shared__ __align__(16) uint32_t s1[];
    uint32_t* AfH = s1;
    uint32_t* AfL = s1 + 4096;
    float* rs = (float*)(s1 + 16448);
    float* To = (float*)s1;
    int tid = threadIdx.x, lane = tid & 31, warp = tid >> 5;
    int wm = warp & 3, wn = warp >> 2;       // 4M x 4N
    int row0 = blockIdx.x * 128;
    uint32_t smem_b = (uint32_t)__cvta_generic_to_shared(s1);
    float c[2][2][4] = {};

    {
        uint32_t dst = smem_b + 8192u * 4u;
        const uint4* src = (const uint4*)g_Bf;
        for (int l = tid; l < 1024; l += 512)
            asm volatile("cp.async.ca.shared.global [%0], [%1], 16;"
                         :: "r"(dst + (uint32_t)l * 16u), "l"(src + l) : "memory");
        asm volatile("cp.async.commit_group;" ::: "memory");
    }

    for (int kc = 0; kc < 8; kc++) {
        __syncthreads();
        for (int l = tid; l < 4096; l += 512) {
            int row = l >> 5, col2 = (l & 31) * 2;
            float2 v = *(const float2*)&x[(size_t)(row0 + row) * KX + kc * 64 + col2];
            uint32_t lo, hi = pack2(v.x, v.y, &lo);
            int w = afragw(row, col2);
            AfH[w] = hi; AfL[w] = lo;
        }
        asm volatile("cp.async.wait_group 0;" ::: "memory");
        __syncthreads();
        if (kc < 7) {
            uint32_t dst = smem_b + (8192u + (uint32_t)((kc + 1) & 1) * 4096u) * 4u;
            const uint4* src = (const uint4*)(g_Bf + (kc + 1) * 4096);
            for (int l = tid; l < 1024; l += 512)
                asm volatile("cp.async.ca.shared.global [%0], [%1], 16;"
                             :: "r"(dst + (uint32_t)l * 16u), "l"(src + l) : "memory");
            asm volatile("cp.async.commit_group;" ::: "memory");
        }
        const uint32_t* BfH = s1 + 8192 + (kc & 1) * 4096;
        const uint32_t* BfL = BfH + 2048;
#pragma unroll
        for (int ks = 0; ks < 4; ks++) {
            uint32_t ah[2][4], al[2][4];
#pragma unroll
            for (int mt = 0; mt < 2; mt++) {
                int base = (((wm * 4 + ks) * 32 + lane) * 2 + mt) * 4;
                *(uint4*)ah[mt] = *(const uint4*)&AfH[base];
                *(uint4*)al[mt] = *(const uint4*)&AfL[base];
            }
            uint32_t bh[2][2], bl[2][2];
#pragma unroll
            for (int nt = 0; nt < 2; nt++) {
                int base = (((wn * 4 + ks) * 2 + nt) * 32 + lane) * 2;
                *(uint2*)bh[nt] = *(const uint2*)&BfH[base];
                *(uint2*)bl[nt] = *(const uint2*)&BfL[base];
            }
#pragma unroll
            for (int mt = 0; mt < 2; mt++)
#pragma unroll
                for (int nt = 0; nt < 2; nt++) {
                    mma_bf16(c[mt][nt], ah[mt], bh[nt]);
                    mma_bf16(c[mt][nt], ah[mt], bl[nt]);
                    mma_bf16(c[mt][nt], al[mt], bh[nt]);
                }
        }
    }
    __syncthreads();
#pragma unroll
    for (int mt = 0; mt < 2; mt++)
#pragma unroll
        for (int nt = 0; nt < 2; nt++)
#pragma unroll
            for (int jp = 0; jp < 2; jp++) {
                int row = wm * 32 + mt * 16 + (lane >> 2) + jp * 8;
                int col = wn * 16 + nt * 8 + (lane & 3) * 2;
                *(float2*)&To[row * 68 + col] =
                    make_float2(c[mt][nt][jp * 2], c[mt][nt][jp * 2 + 1]);
            }
    __syncthreads();
    if (tid < 128) {
        float ss = 0.f;
        const float* rp = &To[tid * 68];
#pragma unroll
        for (int q = 0; q < 16; q++) {
            float4 v = *(const float4*)&rp[q * 4];
            ss += v.x * v.x + v.y * v.y + v.z * v.z + v.w * v.w;
        }
        rs[tid] = 1.0f / fmaxf(sqrtf(ss), 1e-12f);
    }
    __syncthreads();
    for (int l = tid; l < 2048; l += 512) {
        int row = l >> 4, c4 = (l & 15) * 4;
        float sc = rs[row];
        float4 v = *(const float4*)&To[row * 68 + c4];
        v.x *= sc; v.y *= sc; v.z *= sc; v.w *= sc;
        *(float4*)&g_t[(size_t)(row0 + row) * AA + c4] = v;
    }
}

// ================= K2: rep window-sum + per-block moments (fp32 exact) =============
__global__ __launch_bounds__(256) void k2_rep(const float* __restrict__ lw,
                                              const float* __restrict__ lb,
                                              float* __restrict__ orep) {
    __shared__ float ts[143 * 64];
    __shared__ float ws[16 * 64];
    __shared__ float bsum[64];
    __shared__ float mred[4][64];
    int row0 = blockIdx.x * 128;
    int base = row0 - 15;
    int tid = threadIdx.x;
    for (int l = tid; l < 143 * 64; l += 256) {
        int r = l >> 6, a = l & 63;
        int g = base + r; if (g < 0) g = 0;
        ts[l] = g_t[(size_t)g * 64 + a];
    }
    for (int l = tid; l < 1024; l += 256) ws[l] = lw[l];
    if (tid < 64) {
        float s = 0.f;
        for (int j = 0; j < 16; j++) s += lb[j * 64 + tid];
        bsum[tid] = s;
    }
    __syncthreads();
    int a = tid & 63, rg = tid >> 6;
    float ms = 0.f;
    for (int i = 0; i < 32; i++) {
        int r = rg * 32 + i;
        int n = row0 + r;
        float acc = bsum[a];
        if (n >= 15) {
#pragma unroll
            for (int j = 0; j < 16; j++) acc += ws[j * 64 + a] * ts[(r + j) * 64 + a];
        } else {
            for (int j = 0; j < 16; j++) {
                int lj = min(j, n) + 15;
                acc += ws[j * 64 + a] * ts[lj * 64 + a];
            }
        }
        g_rep[(size_t)n * 64 + a] = acc;
        if (orep) orep[(size_t)n * 64 + a] = acc;
        ms += acc;
    }
    mred[rg][a] = ms;
    __syncthreads();
    if (tid < 64)
        g_part[(size_t)blockIdx.x * MOMW + tid] =
            mred[0][tid] + mred[1][tid] + mred[2][tid] + mred[3][tid];
    int bi = tid & 15, ai = tid >> 4;
    int a4 = ai * 4, b4 = bi * 4;
    float sa[4][4] = {};
    const float* rp = &g_rep[(size_t)row0 * 64];
    for (int r = 0; r < 128; r++) {
        float4 av = *(const float4*)&rp[r * 64 + a4];
        float4 bv = *(const float4*)&rp[r * 64 + b4];
        float am[4] = {av.x, av.y, av.z, av.w};
        float bm[4] = {bv.x, bv.y, bv.z, bv.w};
#pragma unroll
        for (int i = 0; i < 4; i++)
#pragma unroll
            for (int j = 0; j < 4; j++) sa[i][j] = fmaf(am[i], bm[j], sa[i][j]);
    }
    float* sp = &g_part[(size_t)blockIdx.x * MOMW + 64];
#pragma unroll
    for (int i = 0; i < 4; i++)
        *(float4*)&sp[(a4 + i) * 64 + b4] = make_float4(sa[i][0], sa[i][1], sa[i][2], sa[i][3]);
}

// ================= K2b: parallel partial reduce (stage 1 of 2) =====================
__global__ __launch_bounds__(128) void k2b() {
    int e = blockIdx.x * 128 + threadIdx.x;
    if (e >= MOMW) return;
    int k0 = blockIdx.y * 64;
    float s0 = 0.f, s1 = 0.f, s2 = 0.f, s3 = 0.f;
    for (int k = k0; k < k0 + 64; k += 4) {
        s0 += g_part[(size_t)(k    ) * MOMW + e];
        s1 += g_part[(size_t)(k + 1) * MOMW + e];
        s2 += g_part[(size_t)(k + 2) * MOMW + e];
        s3 += g_part[(size_t)(k + 3) * MOMW + e];
    }
    g_p2[blockIdx.y * MOMW + e] = (s0 + s1) + (s2 + s3);
}

// ================= K3w: final moment fold + BN affine + pack tower weights =========
__global__ __launch_bounds__(512) void k3w(const float* __restrict__ W1,
                                           const float* __restrict__ W2,
                                           const float* __restrict__ b2,
                                           const float* __restrict__ gamma,
                                           const float* __restrict__ beta) {
    __shared__ float Ss[4096];
    __shared__ float Ws1[64 * 65];
    __shared__ float msx[64];
    __shared__ float qred[8][64], mured[8][64];
    __shared__ float sclS[64], shfS[64];
    int d = blockIdx.x, tid = threadIdx.x;
    for (int e = tid; e < MOMW; e += 512) {
        float s = 0.f;
#pragma unroll
        for (int kc = 0; kc < 8; kc++) s += g_p2[kc * MOMW + e];
        if (e < 64) msx[e] = s; else Ss[e - 64] = s;
    }
    for (int l = tid; l < 4096; l += 512)
        Ws1[(l >> 6) * 65 + (l & 63)] = W1[(size_t)d * 4096 + l];
    __syncthreads();
    int b = tid & 63, iq = tid >> 6;
    float q = 0.f, mu = 0.f;
    for (int i = iq * 8; i < iq * 8 + 8; i++) {
        float wi = Ws1[i * 65 + b];
        mu = fmaf(msx[i], wi, mu);
        float tmp = 0.f;
#pragma unroll 8
        for (int j = 0; j < 64; j++) tmp = fmaf(Ss[i * 64 + j], Ws1[j * 65 + b], tmp);
        q = fmaf(wi, tmp, q);
    }
    qred[iq][b] = q; mured[iq][b] = mu;
    __syncthreads();
    if (tid < 64) {
        float Q = 0.f, MU = 0.f;
#pragma unroll
        for (int r = 0; r < 8; r++) { Q += qred[r][tid]; MU += mured[r][tid]; }
        const float invN = 1.0f / (float)NN;
        float mean = MU * invN;
        float var = Q * invN - mean * mean;
        float s = gamma[d * 64 + tid] * rsqrtf(var + 1e-5f);
        sclS[tid] = s;
        shfS[tid] = beta[d * 64 + tid] - mean * s;
    }
    __syncthreads();
    uint32_t* wf = g_Wf + (size_t)d * WFW;
    const float* w1p = W1 + (size_t)d * 4096;
    for (int l = tid; l < 2048; l += 512) {
        int n = l >> 5, k2 = (l & 31) * 2;
        uint32_t lo, hi = pack2(w1p[k2 * 64 + n], w1p[(k2 + 1) * 64 + n], &lo);
        int wn_ = n >> 4, nt = (n >> 3) & 1, nn = n & 7;
        int ks = k2 >> 4, kI = k2 & 15;
        int ln = nn * 4 + ((kI >> 1) & 3), j = kI >> 3;
        int w = (((wn_ * 4 + ks) * 2 + nt) * 32 + ln) * 2 + j;
        wf[w] = hi; wf[2048 + w] = lo;
    }
    const float* w2p = W2 + (size_t)d * 6144;
    for (int l = tid; l < 3072; l += 512) {
        int n = l >> 5, k2 = (l & 31) * 2;
        uint32_t lo, hi = pack2(w2p[k2 * 96 + n], w2p[(k2 + 1) * 96 + n], &lo);
        int wn2 = n / 24, nr = n - wn2 * 24;
        int nt = nr >> 3, nn = n & 7;
        int ks = k2 >> 4, kI = k2 & 15;
        int ln = nn * 4 + ((kI >> 1) & 3), j = kI >> 3;
        int w = (((wn2 * 4 + ks) * 3 + nt) * 32 + ln) * 2 + j;
        wf[4096 + w] = hi; wf[7168 + w] = lo;
    }
    if (tid < 64) {
        wf[10240 + tid] = __float_as_uint(sclS[tid]);
        wf[10304 + tid] = __float_as_uint(shfS[tid]);
    }
    if (tid >= 128 && tid < 224)
        wf[10368 + tid - 128] = __float_as_uint(b2[d * 96 + tid - 128]);
}

// ================= K4m: towers, 64-row tiles, 3 CTA/SM, split prefetch + discard ===
// dyn smem words: AfH 0 | AfL 2048 | HfH 4096 | HfL 6144 | W 8192..18655
#define K4M_WORDS 18656
#define K4M_SMEM  (K4M_WORDS * 4)
__global__ __launch_bounds__(256, 3) void k4m(float* __restrict__ out) {
    extern __shared__ __align__(16) uint32_t sw[];
    uint32_t* AfH = sw;
    uint32_t* AfL = sw + 2048;
    uint32_t* HfH = sw + 4096;
    uint32_t* HfL = sw + 6144;
    const uint32_t* B1H = sw + 8192;
    const uint32_t* B1L = sw + 10240;
    const uint32_t* B2H = sw + 12288;
    const uint32_t* B2L = sw + 15360;
    const float* scl = (const float*)(sw + 18432);
    const float* shf = (const float*)(sw + 18496);
    const float* b2s = (const float*)(sw + 18560);
    int tid = threadIdx.x;
    int lane = tid & 31, warp = tid >> 5;
    int wm = warp & 1, wn = warp >> 1;     // 2 M-warps x 4 N-warps
    int row0 = blockIdx.x * 64;
    uint32_t smem_b = (uint32_t)__cvta_generic_to_shared(sw);
    uint32_t wdst = smem_b + 8192u * 4u;

    // prefetch full weights d=0
    for (int l = tid; l < WFW / 4; l += 256)
        asm volatile("cp.async.ca.shared.global [%0], [%1], 16;"
                     :: "r"(wdst + (uint32_t)l * 16u), "l"((const uint4*)g_Wf + l) : "memory");
    asm volatile("cp.async.commit_group;" ::: "memory");

    // stage A = rep tile -> hi/lo frags (once)
    for (int l = tid; l < 2048; l += 256) {
        int row = l >> 5, col2 = (l & 31) * 2;
        const float* rp = &g_rep[(size_t)(row0 + row) * 64 + col2];
        uint32_t lo, hi = pack2(rp[0], rp[1], &lo);
        int w = afragw(row, col2);
        AfH[w] = hi; AfL[w] = lo;
    }

    for (int d = 0; d < 8; d++) {
        asm volatile("cp.async.wait_group 0;" ::: "memory");
        __syncthreads();   // weights d fully present; prev iter done

        // ---- GEMM1 ----
        float c1[2][2][4] = {};
#pragma unroll
        for (int ks = 0; ks < 4; ks++) {
            uint32_t ah[2][4], al[2][4];
#pragma unroll
            for (int mt = 0; mt < 2; mt++) {
                int base = (((wm * 4 + ks) * 32 + lane) * 2 + mt) * 4;
                *(uint4*)ah[mt] = *(const uint4*)&AfH[base];
                *(uint4*)al[mt] = *(const uint4*)&AfL[base];
            }
            uint32_t bh[2][2], bl[2][2];
#pragma unroll
            for (int nt = 0; nt < 2; nt++) {
                int base = (((wn * 4 + ks) * 2 + nt) * 32 + lane) * 2;
                *(uint2*)bh[nt] = *(const uint2*)&B1H[base];
                *(uint2*)bl[nt] = *(const uint2*)&B1L[base];
            }
#pragma unroll
            for (int mt = 0; mt < 2; mt++)
#pragma unroll
                for (int nt = 0; nt < 2; nt++) {
                    mma_bf16(c1[mt][nt], ah[mt], bh[nt]);
                    mma_bf16(c1[mt][nt], ah[mt], bl[nt]);
                    mma_bf16(c1[mt][nt], al[mt], bh[nt]);
                }
        }
        // ---- BN + ELU -> Hf ----
#pragma unroll
        for (int mt = 0; mt < 2; mt++)
#pragma unroll
            for (int nt = 0; nt < 2; nt++) {
                int colb = wn * 16 + nt * 8 + (lane & 3) * 2;
                float s0 = scl[colb], s1 = scl[colb + 1];
                float f0 = shf[colb], f1 = shf[colb + 1];
#pragma unroll
                for (int jp = 0; jp < 2; jp++) {
                    int row = wm * 32 + mt * 16 + (lane >> 2) + jp * 8;
                    float v0 = eluf(fmaf(c1[mt][nt][jp * 2 + 0], s0, f0));
                    float v1 = eluf(fmaf(c1[mt][nt][jp * 2 + 1], s1, f1));
                    uint32_t lo, hi = pack2(v0, v1, &lo);
                    int w = afragw(row, colb);
                    HfH[w] = hi; HfL[w] = lo;
                }
            }
        __syncthreads();   // Hf ready; B1 region dead -> prefetch W1(d+1) under GEMM2
        if (d < 7) {
            const uint4* src = (const uint4*)(g_Wf + (size_t)(d + 1) * WFW);
            for (int l = tid; l < 1024; l += 256)   // first 4096 words = B1H/B1L
                asm volatile("cp.async.ca.shared.global [%0], [%1], 16;"
                             :: "r"(wdst + (uint32_t)l * 16u), "l"(src + l) : "memory");
            asm volatile("cp.async.commit_group;" ::: "memory");
        }

        // ---- GEMM2 ----
        float c2[2][3][4] = {};
#pragma unroll
        for (int ks = 0; ks < 4; ks++) {
            uint32_t ah[2][4], al[2][4];
#pragma unroll
            for (int mt = 0; mt < 2; mt++) {
                int base = (((wm * 4 + ks) * 32 + lane) * 2 + mt) * 4;
                *(uint4*)ah[mt] = *(const uint4*)&HfH[base];
                *(uint4*)al[mt] = *(const uint4*)&HfL[base];
            }
            uint32_t bh[3][2], bl[3][2];
#pragma unroll
            for (int nt = 0; nt < 3; nt++) {
                int base = (((wn * 4 + ks) * 3 + nt) * 32 + lane) * 2;
                *(uint2*)bh[nt] = *(const uint2*)&B2H[base];
                *(uint2*)bl[nt] = *(const uint2*)&B2L[base];
            }
#pragma unroll
            for (int mt = 0; mt < 2; mt++)
#pragma unroll
                for (int nt = 0; nt < 3; nt++) {
                    mma_bf16(c2[mt][nt], ah[mt], bh[nt]);
                    mma_bf16(c2[mt][nt], ah[mt], bl[nt]);
                    mma_bf16(c2[mt][nt], al[mt], bh[nt]);
                }
        }
        // fold bias into regs before releasing the weight buffer
#pragma unroll
        for (int mt = 0; mt < 2; mt++)
#pragma unroll
            for (int nt = 0; nt < 3; nt++) {
                int colb = wn * 24 + nt * 8 + (lane & 3) * 2;
                float bb0 = b2s[colb], bb1 = b2s[colb + 1];
                c2[mt][nt][0] += bb0; c2[mt][nt][1] += bb1;
                c2[mt][nt][2] += bb0; c2[mt][nt][3] += bb1;
            }
        __syncthreads();   // all warps done reading W2/params d + Hf

        // prefetch remainder of weights d+1 (B2 + params) under the stores
        if (d < 7) {
            const uint4* src = (const uint4*)(g_Wf + (size_t)(d + 1) * WFW);
            for (int l = 1024 + tid; l < WFW / 4; l += 256)
                asm volatile("cp.async.ca.shared.global [%0], [%1], 16;"
                             :: "r"(wdst + (uint32_t)l * 16u), "l"(src + l) : "memory");
            asm volatile("cp.async.commit_group;" ::: "memory");
        }
        // ---- planar store ----
#pragma unroll
        for (int mt = 0; mt < 2; mt++)
#pragma unroll
            for (int nt = 0; nt < 3; nt++) {
                int colb = wn * 24 + nt * 8 + (lane & 3) * 2;
#pragma unroll
                for (int jp = 0; jp < 2; jp++) {
                    int row = wm * 32 + mt * 16 + (lane >> 2) + jp * 8;
                    *(float2*)&g_Y[((size_t)d * NN + row0 + row) * 96 + colb] =
                        make_float2(c2[mt][nt][jp * 2], c2[mt][nt][jp * 2 + 1]);
                }
            }
    }
    // ---- fused transpose tail: g_Y (L2-resident own stripe) -> interleaved out ----
    __syncthreads();
    for (int l = tid; l < 12288; l += 256) {
        int r = l / 192, q = l - r * 192;
        int v0 = q * 4;
        int col = v0 >> 3, d0 = v0 & 7;   // d0 in {0, 4}
        size_t rowi = (size_t)(row0 + r);
        float4 o;
        o.x = g_Y[((size_t)(d0 + 0) * NN + rowi) * 96 + col];
        o.y = g_Y[((size_t)(d0 + 1) * NN + rowi) * 96 + col];
        o.z = g_Y[((size_t)(d0 + 2) * NN + rowi) * 96 + col];
        o.w = g_Y[((size_t)(d0 + 3) * NN + rowi) * 96 + col];
        *(float4*)&out[rowi * 768 + v0] = o;
    }
    // ---- discard dead g_Y stripe from L2 (skip DRAM writeback) ----
    __syncthreads();   // all reads of the stripe done
#pragma unroll
    for (int d = 0; d < 8; d++) {
        const char* base = (const char*)&g_Y[((size_t)d * NN + row0) * 96];
        for (int l = tid; l < 192; l += 256)   // 64 rows * 384B = 192 x 128B
            asm volatile("discard.global.L2 [%0], 128;" :: "l"(base + l * 128) : "memory");
    }
}

// ---------------- launch ----------------
extern "C" void kernel_launch(void* const* d_in, const int* in_sizes, int n_in,
                              void* d_out, int out_size) {
    const float* x     = (const float*)d_in[0];
    const float* shz   = (const float*)d_in[1];
    const float* lw    = (const float*)d_in[2];
    const float* lb    = (const float*)d_in[3];
    const float* W1    = (const float*)d_in[4];
    // d_in[5] = b1: cancels inside BatchNorm, unused
    const float* gamma = (const float*)d_in[6];
    const float* beta  = (const float*)d_in[7];
    const float* W2    = (const float*)d_in[8];
    const float* b2    = (const float*)d_in[9];
    float* out = (float*)d_out;

    float* orep = nullptr;
    if ((long long)out_size >= (long long)NN * 832)
        orep = out + (size_t)NN * 768;

    cudaFuncSetAttribute(k1m, cudaFuncAttributeMaxDynamicSharedMemorySize, K1_SMEM);
    cudaFuncSetAttribute(k4m, cudaFuncAttributeMaxDynamicSharedMemorySize, K4M_SMEM);

    kprep_b<<<8, 256>>>(shz);                             // launch 0
    k1m<<<NN / 128, 512, K1_SMEM>>>(x);                   // launch 1
    k2_rep<<<NN / 128, 256>>>(lw, lb, orep);              // launch 2
    k2b<<<dim3(33, 8), 128>>>();                          // launch 3
    k3w<<<DD, 512>>>(W1, W2, b2, gamma, beta);            // launch 4
    k4m<<<NN / 64, 256, K4M_SMEM>>>(out);                 // launch 5
}

// round 17
// speedup vs baseline: 1.0214x; 1.0214x over previous
#include <cuda_runtime.h>
#include <cuda_bf16.h>
#include <math.h>
#include <stdint.h>

#define NN   65536
#define KX   512
#define AA   64
#define DD   8
#define PP   96
#define NB2  (NN/128)
#define MOMW (AA + AA*AA)
#define WFW  10464

// ---------------- scratch ----------------
__device__ __align__(16) float g_t  [(size_t)NN*AA];
__device__ __align__(16) float g_rep[(size_t)NN*AA];
__device__ __align__(16) float g_part[(size_t)NB2*MOMW];
__device__ __align__(16) float g_p2[8*MOMW];
__device__ __align__(16) uint32_t g_Wf[DD*WFW];
__device__ __align__(16) uint32_t g_Bf[8*4096];
__device__ __align__(16) float g_Y[(size_t)DD*NN*PP];

__device__ __forceinline__ float eluf(float v) { return v > 0.f ? v : expm1f(v); }

__device__ __forceinline__ uint32_t pack2(float f0, float f1, uint32_t* lo) {
    __nv_bfloat16 h0 = __float2bfloat16(f0);
    __nv_bfloat16 h1 = __float2bfloat16(f1);
    __nv_bfloat16 l0 = __float2bfloat16(f0 - __bfloat162float(h0));
    __nv_bfloat16 l1 = __float2bfloat16(f1 - __bfloat162float(h1));
    *lo = (uint32_t)__bfloat16_as_ushort(l0) | ((uint32_t)__bfloat16_as_ushort(l1) << 16);
    return (uint32_t)__bfloat16_as_ushort(h0) | ((uint32_t)__bfloat16_as_ushort(h1) << 16);
}
__device__ __forceinline__ void mma_bf16(float* c, const uint32_t* a, const uint32_t* b) {
    asm volatile("mma.sync.aligned.m16n8k16.row.col.f32.bf16.bf16.f32 "
                 "{%0,%1,%2,%3}, {%4,%5,%6,%7}, {%8,%9}, {%0,%1,%2,%3};"
                 : "+f"(c[0]), "+f"(c[1]), "+f"(c[2]), "+f"(c[3])
                 : "r"(a[0]), "r"(a[1]), "r"(a[2]), "r"(a[3]), "r"(b[0]), "r"(b[1]));
}
__device__ __forceinline__ int afragw(int row, int col2) {
    int m32 = row >> 5, mt = (row >> 4) & 1, ks = col2 >> 4;
    int rI = row & 15, cI = col2 & 15;
    int ln = (rI & 7) * 4 + ((cI >> 1) & 3);
    int j  = ((cI >> 3) << 1) | (rI >> 3);
    return (((m32 * 4 + ks) * 32 + ln) * 2 + mt) * 4 + j;
}

// ================= Kprep_b: pack shz chunk kc into fragment hi/lo planes ===========
__global__ __launch_bounds__(256) void kprep_b(const float* __restrict__ Bz) {
    __shared__ float Braw[64 * 65];
    int kc = blockIdx.x, tid = threadIdx.x;
    for (int l = tid; l < 4096; l += 256) {
        int k = l >> 6, n = l & 63;
        Braw[k * 65 + n] = Bz[(size_t)(kc * 64 + k) * AA + n];
    }
    __syncthreads();
    uint32_t* dst = g_Bf + kc * 4096;
    for (int l = tid; l < 2048; l += 256) {
        int n = l >> 5, k2 = (l & 31) * 2;
        uint32_t lo, hi = pack2(Braw[k2 * 65 + n], Braw[(k2 + 1) * 65 + n], &lo);
        int wn_ = n >> 4, nt = (n >> 3) & 1, nn = n & 7;
        int ks = k2 >> 4, kI = k2 & 15;
        int ln = nn * 4 + ((kI >> 1) & 3), j = kI >> 3;
        int w = (((wn_ * 4 + ks) * 2 + nt) * 32 + ln) * 2 + j;
        dst[w] = hi; dst[2048 + w] = lo;
    }
}

// ================= K1m: t = normalize_rows(x @ shz), double-buffered A and B =======
// words: Af[2] @ 0 (8192 each: H 4096 + L 4096) | Bf[2] @ 16384 (4096 each) | rs @ 24576
// To aliases words [0, 8704) as [128][68] after mainloop.
#define K1_SMEM (24704 * 4)
__global__ __launch_bounds__(512, 1) void k1m(const float* __restrict__ x) {
    extern __shared__ __align__(16) uint32_t s1[];
    float* rs = (float*)(s1 + 24576);
    float* To = (float*)s1;
    int tid = threadIdx.x, lane = tid & 31, warp = tid >> 5;
    int wm = warp & 3, wn = warp >> 2;       // 4M x 4N
    int row0 = blockIdx.x * 128;
    uint32_t smem_b = (uint32_t)__cvta_generic_to_shared(s1);
    float c[2][2][4] = {};

    // prefetch B chunk 0 -> Bbuf0
    {
        uint32_t dst = smem_b + 16384u * 4u;
        const uint4* src = (const uint4*)g_Bf;
        for (int l = tid; l < 1024; l += 512)
            asm volatile("cp.async.ca.shared.global [%0], [%1], 16;"
                         :: "r"(dst + (uint32_t)l * 16u), "l"(src + l) : "memory");
        asm volatile("cp.async.commit_group;" ::: "memory");
    }
    // stage A chunk 0 -> Afbuf0
    {
        uint32_t* AfH = s1;
        uint32_t* AfL = s1 + 4096;
        for (int l = tid; l < 4096; l += 512) {
            int row = l >> 5, col2 = (l & 31) * 2;
            float2 v = *(const float2*)&x[(size_t)(row0 + row) * KX + col2];
            uint32_t lo, hi = pack2(v.x, v.y, &lo);
            int w = afragw(row, col2);
            AfH[w] = hi; AfL[w] = lo;
        }
    }
    asm volatile("cp.async.wait_group 0;" ::: "memory");
    __syncthreads();

    for (int kc = 0; kc < 8; kc++) {
        int nb = (kc + 1) & 1;
        // prefetch B(kc+1) into alternate buffer (that buffer's readers finished
        // before the sync that ended iteration kc-1)
        if (kc < 7) {
            uint32_t dst = smem_b + (16384u + (uint32_t)nb * 4096u) * 4u;
            const uint4* src = (const uint4*)(g_Bf + (kc + 1) * 4096);
            for (int l = tid; l < 1024; l += 512)
                asm volatile("cp.async.ca.shared.global [%0], [%1], 16;"
                             :: "r"(dst + (uint32_t)l * 16u), "l"(src + l) : "memory");
            asm volatile("cp.async.commit_group;" ::: "memory");
        }
        // MMA(kc) from buffers kc&1
        const uint32_t* AfH = s1 + (kc & 1) * 8192;
        const uint32_t* AfL = AfH + 4096;
        const uint32_t* BfH = s1 + 16384 + (kc & 1) * 4096;
        const uint32_t* BfL = BfH + 2048;
#pragma unroll
        for (int ks = 0; ks < 4; ks++) {
            uint32_t ah[2][4], al[2][4];
#pragma unroll
            for (int mt = 0; mt < 2; mt++) {
                int base = (((wm * 4 + ks) * 32 + lane) * 2 + mt) * 4;
                *(uint4*)ah[mt] = *(const uint4*)&AfH[base];
                *(uint4*)al[mt] = *(const uint4*)&AfL[base];
            }
            uint32_t bh[2][2], bl[2][2];
#pragma unroll
            for (int nt = 0; nt < 2; nt++) {
                int base = (((wn * 4 + ks) * 2 + nt) * 32 + lane) * 2;
                *(uint2*)bh[nt] = *(const uint2*)&BfH[base];
                *(uint2*)bl[nt] = *(const uint2*)&BfL[base];
            }
#pragma unroll
            for (int mt = 0; mt < 2; mt++)
#pragma unroll
                for (int nt = 0; nt < 2; nt++) {
                    mma_bf16(c[mt][nt], ah[mt], bh[nt]);
                    mma_bf16(c[mt][nt], ah[mt], bl[nt]);
                    mma_bf16(c[mt][nt], al[mt], bh[nt]);
                }
        }
        // stage A(kc+1) into alternate Af buffer (safe for same reason)
        if (kc < 7) {
            uint32_t* nAfH = s1 + nb * 8192;
            uint32_t* nAfL = nAfH + 4096;
            for (int l = tid; l < 4096; l += 512) {
                int row = l >> 5, col2 = (l & 31) * 2;
                float2 v = *(const float2*)&x[(size_t)(row0 + row) * KX + (kc + 1) * 64 + col2];
                uint32_t lo, hi = pack2(v.x, v.y, &lo);
                int w = afragw(row, col2);
                nAfH[w] = hi; nAfL[w] = lo;
            }
        }
        asm volatile("cp.async.wait_group 0;" ::: "memory");
        __syncthreads();   // single barrier per chunk
    }
    // ---- epilogue: C frags -> To[128][68], row norms, write g_t ----
#pragma unroll
    for (int mt = 0; mt < 2; mt++)
#pragma unroll
        for (int nt = 0; nt < 2; nt++)
#pragma unroll
            for (int jp = 0; jp < 2; jp++) {
                int row = wm * 32 + mt * 16 + (lane >> 2) + jp * 8;
                int col = wn * 16 + nt * 8 + (lane & 3) * 2;
                *(float2*)&To[row * 68 + col] =
                    make_float2(c[mt][nt][jp * 2], c[mt][nt][jp * 2 + 1]);
            }
    __syncthreads();
    if (tid < 128) {
        float ss = 0.f;
        const float* rp = &To[tid * 68];
#pragma unroll
        for (int q = 0; q < 16; q++) {
            float4 v = *(const float4*)&rp[q * 4];
            ss += v.x * v.x + v.y * v.y + v.z * v.z + v.w * v.w;
        }
        rs[tid] = 1.0f / fmaxf(sqrtf(ss), 1e-12f);
    }
    __syncthreads();
    for (int l = tid; l < 2048; l += 512) {
        int row = l >> 4, c4 = (l & 15) * 4;
        float sc = rs[row];
        float4 v = *(const float4*)&To[row * 68 + c4];
        v.x *= sc; v.y *= sc; v.z *= sc; v.w *= sc;
        *(float4*)&g_t[(size_t)(row0 + row) * AA + c4] = v;
    }
}

// ================= K2: rep window-sum + per-block moments (smem-resident S) ========
// dyn smem words: ts 0..9151 | ws 9152 | bsum 10176 | mred 10240 | reps 10496..18687
#define K2_SMEM (18688 * 4)
__global__ __launch_bounds__(256) void k2_rep(const float* __restrict__ lw,
                                              const float* __restrict__ lb,
                                              float* __restrict__ orep) {
    extern __shared__ __align__(16) float s2[];
    float* ts   = s2;
    float* ws   = s2 + 9152;
    float* bsum = s2 + 10176;
    float* mred = s2 + 10240;   // [4][64]
    float* reps = s2 + 10496;   // [128][64]
    int row0 = blockIdx.x * 128;
    int base = row0 - 15;
    int tid = threadIdx.x;
    for (int l = tid; l < 143 * 64; l += 256) {
        int r = l >> 6, a = l & 63;
        int g = base + r; if (g < 0) g = 0;
        ts[l] = g_t[(size_t)g * 64 + a];
    }
    for (int l = tid; l < 1024; l += 256) ws[l] = lw[l];
    if (tid < 64) {
        float s = 0.f;
        for (int j = 0; j < 16; j++) s += lb[j * 64 + tid];
        bsum[tid] = s;
    }
    __syncthreads();
    int a = tid & 63, rg = tid >> 6;
    float ms = 0.f;
    for (int i = 0; i < 32; i++) {
        int r = rg * 32 + i;
        int n = row0 + r;
        float acc = bsum[a];
        if (n >= 15) {
#pragma unroll
            for (int j = 0; j < 16; j++) acc += ws[j * 64 + a] * ts[(r + j) * 64 + a];
        } else {
            for (int j = 0; j < 16; j++) {
                int lj = min(j, n) + 15;
                acc += ws[j * 64 + a] * ts[lj * 64 + a];
            }
        }
        g_rep[(size_t)n * 64 + a] = acc;
        if (orep) orep[(size_t)n * 64 + a] = acc;
        reps[r * 64 + a] = acc;
        ms += acc;
    }
    mred[rg * 64 + a] = ms;
    __syncthreads();
    if (tid < 64)
        g_part[(size_t)blockIdx.x * MOMW + tid] =
            mred[0 * 64 + tid] + mred[1 * 64 + tid] + mred[2 * 64 + tid] + mred[3 * 64 + tid];
    int bi = tid & 15, ai = tid >> 4;
    int a4 = ai * 4, b4 = bi * 4;
    float sa[4][4] = {};
    for (int r = 0; r < 128; r++) {
        float4 av = *(const float4*)&reps[r * 64 + a4];
        float4 bv = *(const float4*)&reps[r * 64 + b4];
        float am[4] = {av.x, av.y, av.z, av.w};
        float bm[4] = {bv.x, bv.y, bv.z, bv.w};
#pragma unroll
        for (int i = 0; i < 4; i++)
#pragma unroll
            for (int j = 0; j < 4; j++) sa[i][j] = fmaf(am[i], bm[j], sa[i][j]);
    }
    float* sp = &g_part[(size_t)blockIdx.x * MOMW + 64];
#pragma unroll
    for (int i = 0; i < 4; i++)
        *(float4*)&sp[(a4 + i) * 64 + b4] = make_float4(sa[i][0], sa[i][1], sa[i][2], sa[i][3]);
}

// ================= K2b: parallel partial reduce =====================
__global__ __launch_bounds__(128) void k2b() {
    int e = blockIdx.x * 128 + threadIdx.x;
    if (e >= MOMW) return;
    int k0 = blockIdx.y * 64;
    float s0 = 0.f, s1 = 0.f, s2 = 0.f, s3 = 0.f;
    for (int k = k0; k < k0 + 64; k += 4) {
        s0 += g_part[(size_t)(k    ) * MOMW + e];
        s1 += g_part[(size_t)(k + 1) * MOMW + e];
        s2 += g_part[(size_t)(k + 2) * MOMW + e];
        s3 += g_part[(size_t)(k + 3) * MOMW + e];
    }
    g_p2[blockIdx.y * MOMW + e] = (s0 + s1) + (s2 + s3);
}

// ================= K3w: final moment fold + BN affine + pack tower weights =========
__global__ __launch_bounds__(512) void k3w(const float* __restrict__ W1,
                                           const float* __restrict__ W2,
                                           const float* __restrict__ b2,
                                           const float* __restrict__ gamma,
                                           const float* __restrict__ beta) {
    __shared__ float Ss[4096];
    __shared__ float Ws1[64 * 65];
    __shared__ float msx[64];
    __shared__ float qred[8][64], mured[8][64];
    __shared__ float sclS[64], shfS[64];
    int d = blockIdx.x, tid = threadIdx.x;
    for (int e = tid; e < MOMW; e += 512) {
        float s = 0.f;
#pragma unroll
        for (int kc = 0; kc < 8; kc++) s += g_p2[kc * MOMW + e];
        if (e < 64) msx[e] = s; else Ss[e - 64] = s;
    }
    for (int l = tid; l < 4096; l += 512)
        Ws1[(l >> 6) * 65 + (l & 63)] = W1[(size_t)d * 4096 + l];
    __syncthreads();
    int b = tid & 63, iq = tid >> 6;
    float q = 0.f, mu = 0.f;
    for (int i = iq * 8; i < iq * 8 + 8; i++) {
        float wi = Ws1[i * 65 + b];
        mu = fmaf(msx[i], wi, mu);
        float tmp = 0.f;
#pragma unroll 8
        for (int j = 0; j < 64; j++) tmp = fmaf(Ss[i * 64 + j], Ws1[j * 65 + b], tmp);
        q = fmaf(wi, tmp, q);
    }
    qred[iq][b] = q; mured[iq][b] = mu;
    __syncthreads();
    if (tid < 64) {
        float Q = 0.f, MU = 0.f;
#pragma unroll
        for (int r = 0; r < 8; r++) { Q += qred[r][tid]; MU += mured[r][tid]; }
        const float invN = 1.0f / (float)NN;
        float mean = MU * invN;
        float var = Q * invN - mean * mean;
        float s = gamma[d * 64 + tid] * rsqrtf(var + 1e-5f);
        sclS[tid] = s;
        shfS[tid] = beta[d * 64 + tid] - mean * s;
    }
    __syncthreads();
    uint32_t* wf = g_Wf + (size_t)d * WFW;
    const float* w1p = W1 + (size_t)d * 4096;
    for (int l = tid; l < 2048; l += 512) {
        int n = l >> 5, k2 = (l & 31) * 2;
        uint32_t lo, hi = pack2(w1p[k2 * 64 + n], w1p[(k2 + 1) * 64 + n], &lo);
        int wn_ = n >> 4, nt = (n >> 3) & 1, nn = n & 7;
        int ks = k2 >> 4, kI = k2 & 15;
        int ln = nn * 4 + ((kI >> 1) & 3), j = kI >> 3;
        int w = (((wn_ * 4 + ks) * 2 + nt) * 32 + ln) * 2 + j;
        wf[w] = hi; wf[2048 + w] = lo;
    }
    const float* w2p = W2 + (size_t)d * 6144;
    for (int l = tid; l < 3072; l += 512) {
        int n = l >> 5, k2 = (l & 31) * 2;
        uint32_t lo, hi = pack2(w2p[k2 * 96 + n], w2p[(k2 + 1) * 96 + n], &lo);
        int wn2 = n / 24, nr = n - wn2 * 24;
        int nt = nr >> 3, nn = n & 7;
        int ks = k2 >> 4, kI = k2 & 15;
        int ln = nn * 4 + ((kI >> 1) & 3), j = kI >> 3;
        int w = (((wn2 * 4 + ks) * 3 + nt) * 32 + ln) * 2 + j;
        wf[4096 + w] = hi; wf[7168 + w] = lo;
    }
    if (tid < 64) {
        wf[10240 + tid] = __float_as_uint(sclS[tid]);
        wf[10304 + tid] = __float_as_uint(shfS[tid]);
    }
    if (tid >= 128 && tid < 224)
        wf[10368 + tid - 128] = __float_as_uint(b2[d * 96 + tid - 128]);
}

// ================= K4m: towers, 64-row tiles, 3 CTA/SM, single Wbuf (R15) ==========
#define K4M_WORDS 18656
#define K4M_SMEM  (K4M_WORDS * 4)
__global__ __launch_bounds__(256, 3) void k4m(float* __restrict__ out) {
    extern __shared__ __align__(16) uint32_t sw[];
    uint32_t* AfH = sw;
    uint32_t* AfL = sw + 2048;
    uint32_t* HfH = sw + 4096;
    uint32_t* HfL = sw + 6144;
    const uint32_t* B1H = sw + 8192;
    const uint32_t* B1L = sw + 10240;
    const uint32_t* B2H = sw + 12288;
    const uint32_t* B2L = sw + 15360;
    const float* scl = (const float*)(sw + 18432);
    const float* shf = (const float*)(sw + 18496);
    const float* b2s = (const float*)(sw + 18560);
    int tid = threadIdx.x;
    int lane = tid & 31, warp = tid >> 5;
    int wm = warp & 1, wn = warp >> 1;
    int row0 = blockIdx.x * 64;
    uint32_t smem_b = (uint32_t)__cvta_generic_to_shared(sw);
    uint32_t wdst = smem_b + 8192u * 4u;

    for (int l = tid; l < WFW / 4; l += 256)
        asm volatile("cp.async.ca.shared.global [%0], [%1], 16;"
                     :: "r"(wdst + (uint32_t)l * 16u), "l"((const uint4*)g_Wf + l) : "memory");
    asm volatile("cp.async.commit_group;" ::: "memory");

    for (int l = tid; l < 2048; l += 256) {
        int row = l >> 5, col2 = (l & 31) * 2;
        const float* rp = &g_rep[(size_t)(row0 + row) * 64 + col2];
        uint32_t lo, hi = pack2(rp[0], rp[1], &lo);
        int w = afragw(row, col2);
        AfH[w] = hi; AfL[w] = lo;
    }

    for (int d = 0; d < 8; d++) {
        asm volatile("cp.async.wait_group 0;" ::: "memory");
        __syncthreads();

        float c1[2][2][4] = {};
#pragma unroll
        for (int ks = 0; ks < 4; ks++) {
            uint32_t ah[2][4], al[2][4];
#pragma unroll
            for (int mt = 0; mt < 2; mt++) {
                int base = (((wm * 4 + ks) * 32 + lane) * 2 + mt) * 4;
                *(uint4*)ah[mt] = *(const uint4*)&AfH[base];
                *(uint4*)al[mt] = *(const uint4*)&AfL[base];
            }
            uint32_t bh[2][2], bl[2][2];
#pragma unroll
            for (int nt = 0; nt < 2; nt++) {
                int base = (((wn * 4 + ks) * 2 + nt) * 32 + lane) * 2;
                *(uint2*)bh[nt] = *(const uint2*)&B1H[base];
                *(uint2*)bl[nt] = *(const uint2*)&B1L[base];
            }
#pragma unroll
            for (int mt = 0; mt < 2; mt++)
#pragma unroll
                for (int nt = 0; nt < 2; nt++) {
                    mma_bf16(c1[mt][nt], ah[mt], bh[nt]);
                    mma_bf16(c1[mt][nt], ah[mt], bl[nt]);
                    mma_bf16(c1[mt][nt], al[mt], bh[nt]);
                }
        }
#pragma unroll
        for (int mt = 0; mt < 2; mt++)
#pragma unroll
            for (int nt = 0; nt < 2; nt++) {
                int colb = wn * 16 + nt * 8 + (lane & 3) * 2;
                float s0 = scl[colb], s1 = scl[colb + 1];
                float f0 = shf[colb], f1 = shf[colb + 1];
#pragma unroll
                for (int jp = 0; jp < 2; jp++) {
                    int row = wm * 32 + mt * 16 + (lane >> 2) + jp * 8;
                    float v0 = eluf(fmaf(c1[mt][nt][jp * 2 + 0], s0, f0));
                    float v1 = eluf(fmaf(c1[mt][nt][jp * 2 + 1], s1, f1));
                    uint32_t lo, hi = pack2(v0, v1, &lo);
                    int w = afragw(row, colb);
                    HfH[w] = hi; HfL[w] = lo;
                }
            }
        __syncthreads();

        float c2[2][3][4] = {};
#pragma unroll
        for (int ks = 0; ks < 4; ks++) {
            uint32_t ah[2][4], al[2][4];
#pragma unroll
            for (int mt = 0; mt < 2; mt++) {
                int base = (((wm * 4 + ks) * 32 + lane) * 2 + mt) * 4;
                *(uint4*)ah[mt] = *(const uint4*)&HfH[base];
                *(uint4*)al[mt] = *(const uint4*)&HfL[base];
            }
            uint32_t bh[3][2], bl[3][2];
#pragma unroll
            for (int nt = 0; nt < 3; nt++) {
                int base = (((wn * 4 + ks) * 3 + nt) * 32 + lane) * 2;
                *(uint2*)bh[nt] = *(const uint2*)&B2H[base];
                *(uint2*)bl[nt] = *(const uint2*)&B2L[base];
            }
#pragma unroll
            for (int mt = 0; mt < 2; mt++)
#pragma unroll
                for (int nt = 0; nt < 3; nt++) {
                    mma_bf16(c2[mt][nt], ah[mt], bh[nt]);
                    mma_bf16(c2[mt][nt], ah[mt], bl[nt]);
                    mma_bf16(c2[mt][nt], al[mt], bh[nt]);
                }
        }
#pragma unroll
        for (int mt = 0; mt < 2; mt++)
#pragma unroll
            for (int nt = 0; nt < 3; nt++) {
                int colb = wn * 24 + nt * 8 + (lane & 3) * 2;
                float bb0 = b2s[colb], bb1 = b2s[colb + 1];
                c2[mt][nt][0] += bb0; c2[mt][nt][1] += bb1;
                c2[mt][nt][2] += bb0; c2[mt][nt][3] += bb1;
            }
        __syncthreads();

        if (d < 7) {
            const uint4* src = (const uint4*)(g_Wf + (size_t)(d + 1) * WFW);
            for (int l = tid; l < WFW / 4; l += 256)
                asm volatile("cp.async.ca.shared.global [%0], [%1], 16;"
                             :: "r"(wdst + (uint32_t)l * 16u), "l"(src + l) : "memory");
            asm volatile("cp.async.commit_group;" ::: "memory");
        }
#pragma unroll
        for (int mt = 0; mt < 2; mt++)
#pragma unroll
            for (int nt = 0; nt < 3; nt++) {
                int colb = wn * 24 + nt * 8 + (lane & 3) * 2;
#pragma unroll
                for (int jp = 0; jp < 2; jp++) {
                    int row = wm * 32 + mt * 16 + (lane >> 2) + jp * 8;
                    *(float2*)&g_Y[((size_t)d * NN + row0 + row) * 96 + colb] =
                        make_float2(c2[mt][nt][jp * 2], c2[mt][nt][jp * 2 + 1]);
                }
            }
    }
    __syncthreads();
    for (int l = tid; l < 12288; l += 256) {
        int r = l / 192, q = l - r * 192;
        int v0 = q * 4;
        int col = v0 >> 3, d0 = v0 & 7;
        size_t rowi = (size_t)(row0 + r);
        float4 o;
        o.x = g_Y[((size_t)(d0 + 0) * NN + rowi) * 96 + col];
        o.y = g_Y[((size_t)(d0 + 1) * NN + rowi) * 96 + col];
        o.z = g_Y[((size_t)(d0 + 2) * NN + rowi) * 96 + col];
        o.w = g_Y[((size_t)(d0 + 3) * NN + rowi) * 96 + col];
        *(float4*)&out[rowi * 768 + v0] = o;
    }
}

// ---------------- launch ----------------
extern "C" void kernel_launch(void* const* d_in, const int* in_sizes, int n_in,
                              void* d_out, int out_size) {
    const float* x     = (const float*)d_in[0];
    const float* shz   = (const float*)d_in[1];
    const float* lw    = (const float*)d_in[2];
    const float* lb    = (const float*)d_in[3];
    const float* W1    = (const float*)d_in[4];
    // d_in[5] = b1: cancels inside BatchNorm, unused
    const float* gamma = (const float*)d_in[6];
    const float* beta  = (const float*)d_in[7];
    const float* W2    = (const float*)d_in[8];
    const float* b2    = (const float*)d_in[9];
    float* out = (float*)d_out;

    float* orep = nullptr;
    if ((long long)out_size >= (long long)NN * 832)
        orep = out + (size_t)NN * 768;

    cudaFuncSetAttribute(k1m, cudaFuncAttributeMaxDynamicSharedMemorySize, K1_SMEM);
    cudaFuncSetAttribute(k2_rep, cudaFuncAttributeMaxDynamicSharedMemorySize, K2_SMEM);
    cudaFuncSetAttribute(k4m, cudaFuncAttributeMaxDynamicSharedMemorySize, K4M_SMEM);

    kprep_b<<<8, 256>>>(shz);                             // launch 0
    k1m<<<NN / 128, 512, K1_SMEM>>>(x);                   // launch 1
    k2_rep<<<NN / 128, 256, K2_SMEM>>>(lw, lb, orep);     // launch 2
    k2b<<<dim3(33, 8), 128>>>();                          // launch 3
    k3w<<<DD, 512>>>(W1, W2, b2, gamma, beta);            // launch 4
    k4m<<<NN / 64, 256, K4M_SMEM>>>(out);                 // launch 5
}